// round 1
// baseline (speedup 1.0000x reference)
#include <cuda_runtime.h>
#include <math.h>

#define B 2
#define S 2048
#define D 768
#define H 12
#define E 64
#define BS (B*S)   // 4096

// ---- scratch (static device globals; no runtime allocation) ----
__device__ float g_qkv[(size_t)3 * H * BS * E];   // 37.75 MB : [which][h][b*S + s][e]
__device__ float g_att[(size_t)BS * D];           // 12.6 MB  : [b*S + s][h*E + e]

// =====================================================================
// Kernel 1: fused QKV projection.  For each (which, h):
//   out[m][e] = sum_k x[m][k] * W[which][h][k][e] + b[which][h][e]
// M = 4096, K = 768, N = 64.  64x64 block tile, 256 thr, 4x4 per thread.
// =====================================================================
__global__ __launch_bounds__(256) void qkv_kernel(
    const float* __restrict__ x,
    const float* __restrict__ Wq, const float* __restrict__ bq,
    const float* __restrict__ Wk, const float* __restrict__ bk,
    const float* __restrict__ Wv, const float* __restrict__ bv)
{
    const int m0 = blockIdx.x * 64;
    const int z  = blockIdx.y;          // 0..3*H-1
    const int which = z / H;
    const int h     = z % H;
    const float* W    = (which == 0) ? Wq : (which == 1) ? Wk : Wv;
    const float* bias = (which == 0) ? bq : (which == 1) ? bk : bv;
    W    += (size_t)h * D * E;
    bias += h * E;
    float* out = g_qkv + ((size_t)which * H + h) * (size_t)BS * E;

    __shared__ float Xs[32][65];   // [k][m]
    __shared__ float Ws[32][65];   // [k][n]

    const int t  = threadIdx.x;
    const int tx = t & 15, ty = t >> 4;

    float acc[4][4] = {};

    for (int k0 = 0; k0 < D; k0 += 32) {
        #pragma unroll
        for (int i = 0; i < 8; i++) {              // 64x32 elems
            int idx = i * 256 + t;
            int mm = idx >> 5, kk = idx & 31;
            Xs[kk][mm] = x[(size_t)(m0 + mm) * D + (k0 + kk)];
        }
        #pragma unroll
        for (int i = 0; i < 8; i++) {              // 32x64 elems
            int idx = i * 256 + t;
            int kk = idx >> 6, nn = idx & 63;
            Ws[kk][nn] = W[(size_t)(k0 + kk) * E + nn];
        }
        __syncthreads();
        #pragma unroll 8
        for (int kk = 0; kk < 32; kk++) {
            float xv[4], wv[4];
            #pragma unroll
            for (int i = 0; i < 4; i++) xv[i] = Xs[kk][ty * 4 + i];
            #pragma unroll
            for (int j = 0; j < 4; j++) wv[j] = Ws[kk][tx * 4 + j];
            #pragma unroll
            for (int i = 0; i < 4; i++)
                #pragma unroll
                for (int j = 0; j < 4; j++)
                    acc[i][j] += xv[i] * wv[j];
        }
        __syncthreads();
    }

    #pragma unroll
    for (int i = 0; i < 4; i++) {
        int m = m0 + ty * 4 + i;
        #pragma unroll
        for (int j = 0; j < 4; j++) {
            int n = tx * 4 + j;
            out[(size_t)m * E + n] = acc[i][j] + bias[n];
        }
    }
}

// =====================================================================
// Kernel 2: fp32 flash attention per (h, b).
// Br = Bc = 64, 256 threads, each thread owns a 4x4 patch.
// Online softmax; additive mask streamed from gmem.
// Output written to g_att in [b][s][h][e] (= concat-heads) layout.
// Dynamic smem: Qs[64][65] (Q^T), Ks[64][65] (K^T), Vs[64][65], Ps[64][65] (P^T)
// =====================================================================
__global__ __launch_bounds__(256) void attn_kernel(const float* __restrict__ mask_all)
{
    extern __shared__ float sm[];
    float (*Qs)[65] = (float(*)[65])(sm);              // [e][r]
    float (*Ks)[65] = (float(*)[65])(sm + 64 * 65);    // [e][c]
    float (*Vs)[65] = (float(*)[65])(sm + 2 * 64 * 65);// [c][e]
    float (*Ps)[65] = (float(*)[65])(sm + 3 * 64 * 65);// [c][r]

    const int q0 = blockIdx.x * 64;
    const int hb = blockIdx.y;
    const int h = hb / B, b = hb % B;

    const float* Q = g_qkv + ((size_t)0 * H + h) * (size_t)BS * E + (size_t)b * S * E;
    const float* K = g_qkv + ((size_t)1 * H + h) * (size_t)BS * E + (size_t)b * S * E;
    const float* V = g_qkv + ((size_t)2 * H + h) * (size_t)BS * E + (size_t)b * S * E;
    const float* mask = mask_all + (size_t)(h * B + b) * S * S;

    const int t  = threadIdx.x;
    const int tx = t & 15, ty = t >> 4;

    // Load Q tile (transposed into Qs[e][r])
    #pragma unroll
    for (int i = 0; i < 16; i++) {
        int idx = i * 256 + t;
        int r = idx >> 6, e = idx & 63;
        Qs[e][r] = Q[(size_t)(q0 + r) * E + e];
    }

    float m_i[4], l_i[4], o[4][4];
    #pragma unroll
    for (int i = 0; i < 4; i++) {
        m_i[i] = -INFINITY; l_i[i] = 0.f;
        #pragma unroll
        for (int j = 0; j < 4; j++) o[i][j] = 0.f;
    }
    __syncthreads();

    for (int j0 = 0; j0 < S; j0 += 64) {
        // Load K (transposed) and V tiles
        #pragma unroll
        for (int i = 0; i < 16; i++) {
            int idx = i * 256 + t;
            int c = idx >> 6, e = idx & 63;
            Ks[e][c] = K[(size_t)(j0 + c) * E + e];
            Vs[c][e] = V[(size_t)(j0 + c) * E + e];
        }
        __syncthreads();

        // S = Q K^T  (4x4 per thread)
        float s[4][4] = {};
        #pragma unroll 8
        for (int e = 0; e < 64; e++) {
            float qv[4], kv[4];
            #pragma unroll
            for (int i = 0; i < 4; i++) qv[i] = Qs[e][ty * 4 + i];
            #pragma unroll
            for (int j = 0; j < 4; j++) kv[j] = Ks[e][tx * 4 + j];
            #pragma unroll
            for (int i = 0; i < 4; i++)
                #pragma unroll
                for (int j = 0; j < 4; j++)
                    s[i][j] += qv[i] * kv[j];
        }

        // additive mask (vectorized gmem read; rows are 8KB-aligned)
        #pragma unroll
        for (int i = 0; i < 4; i++) {
            const float4 mv = *(const float4*)(mask + (size_t)(q0 + ty * 4 + i) * S + (j0 + tx * 4));
            s[i][0] += mv.x; s[i][1] += mv.y; s[i][2] += mv.z; s[i][3] += mv.w;
        }

        // online softmax per row (row spread over 16 lanes of same ty)
        #pragma unroll
        for (int i = 0; i < 4; i++) {
            float mx = fmaxf(fmaxf(s[i][0], s[i][1]), fmaxf(s[i][2], s[i][3]));
            #pragma unroll
            for (int off = 8; off > 0; off >>= 1)
                mx = fmaxf(mx, __shfl_xor_sync(0xffffffffu, mx, off, 16));
            float m_new = fmaxf(m_i[i], mx);
            float alpha = __expf(m_i[i] - m_new);
            float p[4], ps = 0.f;
            #pragma unroll
            for (int j = 0; j < 4; j++) { p[j] = __expf(s[i][j] - m_new); ps += p[j]; }
            #pragma unroll
            for (int off = 8; off > 0; off >>= 1)
                ps += __shfl_xor_sync(0xffffffffu, ps, off, 16);
            l_i[i] = l_i[i] * alpha + ps;
            m_i[i] = m_new;
            #pragma unroll
            for (int j = 0; j < 4; j++) o[i][j] *= alpha;
            #pragma unroll
            for (int j = 0; j < 4; j++) Ps[tx * 4 + j][ty * 4 + i] = p[j];
        }
        __syncthreads();

        // O += P V
        #pragma unroll 8
        for (int c = 0; c < 64; c++) {
            float pv[4], vv[4];
            #pragma unroll
            for (int i = 0; i < 4; i++) pv[i] = Ps[c][ty * 4 + i];
            #pragma unroll
            for (int j = 0; j < 4; j++) vv[j] = Vs[c][tx * 4 + j];
            #pragma unroll
            for (int i = 0; i < 4; i++)
                #pragma unroll
                for (int j = 0; j < 4; j++)
                    o[i][j] += pv[i] * vv[j];
        }
        __syncthreads();
    }

    // epilogue: normalize and write concat-head layout [b][s][h][e]
    #pragma unroll
    for (int i = 0; i < 4; i++) {
        float inv = 1.f / l_i[i];
        int srow = q0 + ty * 4 + i;
        #pragma unroll
        for (int j = 0; j < 4; j++) {
            int e = tx * 4 + j;
            g_att[((size_t)(b * S + srow) * H + h) * E + e] = o[i][j] * inv;
        }
    }
}

// =====================================================================
// Kernel 3: output projection.  out = g_att[4096,768] @ Wo[768,768] + bo
// =====================================================================
__global__ __launch_bounds__(256) void proj_kernel(
    const float* __restrict__ Wo, const float* __restrict__ bo,
    float* __restrict__ out)
{
    const int m0 = blockIdx.x * 64;
    const int n0 = blockIdx.y * 64;

    __shared__ float Xs[32][65];   // [k][m]
    __shared__ float Ws[32][65];   // [k][n]

    const int t  = threadIdx.x;
    const int tx = t & 15, ty = t >> 4;

    float acc[4][4] = {};

    for (int k0 = 0; k0 < D; k0 += 32) {
        #pragma unroll
        for (int i = 0; i < 8; i++) {
            int idx = i * 256 + t;
            int mm = idx >> 5, kk = idx & 31;
            Xs[kk][mm] = g_att[(size_t)(m0 + mm) * D + (k0 + kk)];
        }
        #pragma unroll
        for (int i = 0; i < 8; i++) {
            int idx = i * 256 + t;
            int kk = idx >> 6, nn = idx & 63;
            Ws[kk][nn] = Wo[(size_t)(k0 + kk) * D + (n0 + nn)];
        }
        __syncthreads();
        #pragma unroll 8
        for (int kk = 0; kk < 32; kk++) {
            float xv[4], wv[4];
            #pragma unroll
            for (int i = 0; i < 4; i++) xv[i] = Xs[kk][ty * 4 + i];
            #pragma unroll
            for (int j = 0; j < 4; j++) wv[j] = Ws[kk][tx * 4 + j];
            #pragma unroll
            for (int i = 0; i < 4; i++)
                #pragma unroll
                for (int j = 0; j < 4; j++)
                    acc[i][j] += xv[i] * wv[j];
        }
        __syncthreads();
    }

    #pragma unroll
    for (int i = 0; i < 4; i++) {
        int m = m0 + ty * 4 + i;
        #pragma unroll
        for (int j = 0; j < 4; j++) {
            int n = n0 + tx * 4 + j;
            out[(size_t)m * D + n] = acc[i][j] + bo[n];
        }
    }
}

// =====================================================================
// Launch
// =====================================================================
extern "C" void kernel_launch(void* const* d_in, const int* in_sizes, int n_in,
                              void* d_out, int out_size)
{
    const float* x    = (const float*)d_in[0];
    const float* mask = (const float*)d_in[1];
    const float* Wq   = (const float*)d_in[2];
    const float* bq   = (const float*)d_in[3];
    const float* Wk   = (const float*)d_in[4];
    const float* bk   = (const float*)d_in[5];
    const float* Wv   = (const float*)d_in[6];
    const float* bv   = (const float*)d_in[7];
    const float* Wo   = (const float*)d_in[8];
    const float* bo   = (const float*)d_in[9];

    const int smem_attn = 4 * 64 * 65 * (int)sizeof(float);  // 66,560 B
    cudaFuncSetAttribute(attn_kernel, cudaFuncAttributeMaxDynamicSharedMemorySize, smem_attn);

    qkv_kernel <<< dim3(BS / 64, 3 * H), 256 >>>(x, Wq, bq, Wk, bk, Wv, bv);
    attn_kernel<<< dim3(S / 64, H * B), 256, smem_attn >>>(mask);
    proj_kernel<<< dim3(BS / 64, D / 64), 256 >>>(Wo, bo, (float*)d_out);
}

// round 2
// speedup vs baseline: 1.4627x; 1.4627x over previous
#include <cuda_runtime.h>
#include <math.h>

#define B 2
#define S 2048
#define D 768
#define H 12
#define E 64
#define BS (B*S)   // 4096

// ---- scratch (static device globals; no runtime allocation) ----
__device__ float g_qkv[(size_t)3 * H * BS * E];   // [which][h][b*S+s][e]
__device__ float g_att[(size_t)BS * D];           // [b*S+s][h*E+e]

// =====================================================================
// Kernel 1: fused QKV projection. Block tile: 128 (M) x 128 (2 heads' E)
// 256 threads, 8x8 per thread (split 4+4), float4 smem accesses.
// =====================================================================
__global__ __launch_bounds__(256, 2) void qkv_kernel(
    const float* __restrict__ x,
    const float* __restrict__ Wq, const float* __restrict__ bq,
    const float* __restrict__ Wk, const float* __restrict__ bk,
    const float* __restrict__ Wv, const float* __restrict__ bv)
{
    const int m0 = blockIdx.x * 128;
    const int zz = blockIdx.y;              // 0..17
    const int which = zz / (H / 2);         // 0..2
    const int h0 = (zz % (H / 2)) * 2;      // even head
    const float* W    = (which == 0) ? Wq : (which == 1) ? Wk : Wv;
    const float* bias = (which == 0) ? bq : (which == 1) ? bk : bv;
    float* out = g_qkv + (size_t)which * H * BS * E;

    __shared__ float As[32][132];   // [k][m]
    __shared__ float Bs[32][132];   // [k][n]  n: head0 e | head1 e

    const int t  = threadIdx.x;
    const int tx = t & 15, ty = t >> 4;

    float acc[8][8] = {};

    for (int k0 = 0; k0 < D; k0 += 32) {
        // A = x[m][k] -> As[k][m] (transpose via float4 gmem + scalar STS)
        #pragma unroll
        for (int i = 0; i < 4; i++) {
            int f = i * 256 + t;
            int r = f >> 3, cg = (f & 7) * 4;
            float4 v = *(const float4*)(x + (size_t)(m0 + r) * D + k0 + cg);
            As[cg + 0][r] = v.x; As[cg + 1][r] = v.y;
            As[cg + 2][r] = v.z; As[cg + 3][r] = v.w;
        }
        // B = W[h][k][e] -> Bs[k][n] direct float4
        #pragma unroll
        for (int i = 0; i < 4; i++) {
            int f = i * 256 + t;
            int kk = f >> 5, n = (f & 31) * 4;
            int hh = h0 + (n >> 6);
            int e  = n & 63;
            *(float4*)&Bs[kk][n] =
                *(const float4*)(W + ((size_t)hh * D + (k0 + kk)) * E + e);
        }
        __syncthreads();

        #pragma unroll 8
        for (int kk = 0; kk < 32; kk++) {
            float av[8], bv_[8];
            *(float4*)&av[0]  = *(float4*)&As[kk][ty * 4];
            *(float4*)&av[4]  = *(float4*)&As[kk][64 + ty * 4];
            *(float4*)&bv_[0] = *(float4*)&Bs[kk][tx * 4];
            *(float4*)&bv_[4] = *(float4*)&Bs[kk][64 + tx * 4];
            #pragma unroll
            for (int i = 0; i < 8; i++)
                #pragma unroll
                for (int j = 0; j < 8; j++)
                    acc[i][j] += av[i] * bv_[j];
        }
        __syncthreads();
    }

    // bias for this thread's 8 columns
    float bb[8];
    *(float4*)&bb[0] = *(const float4*)(bias + (size_t)h0 * E + tx * 4);
    *(float4*)&bb[4] = *(const float4*)(bias + (size_t)(h0 + 1) * E + tx * 4);

    #pragma unroll
    for (int i = 0; i < 8; i++) {
        int m = m0 + ((i < 4) ? (ty * 4 + i) : (64 + ty * 4 + i - 4));
        #pragma unroll
        for (int jg = 0; jg < 2; jg++) {
            float4 v;
            v.x = acc[i][jg * 4 + 0] + bb[jg * 4 + 0];
            v.y = acc[i][jg * 4 + 1] + bb[jg * 4 + 1];
            v.z = acc[i][jg * 4 + 2] + bb[jg * 4 + 2];
            v.w = acc[i][jg * 4 + 3] + bb[jg * 4 + 3];
            *(float4*)(out + ((size_t)(h0 + jg) * BS + m) * E + tx * 4) = v;
        }
    }
}

// =====================================================================
// Kernel 2: fp32 flash attention. Br = Bc = 128, 256 threads.
// s tile 8x8 per thread; o tile 8x4 (E=64). P stored [r][c] row-major.
// =====================================================================
__global__ __launch_bounds__(256, 1) void attn_kernel(const float* __restrict__ mask_all)
{
    extern __shared__ float sm[];
    float (*Qs)[132] = (float(*)[132])(sm);                    // [e][r] 64x132
    float (*Ks)[132] = (float(*)[132])(sm + 64 * 132);         // [e][c] 64x132
    float (*Vs)[68]  = (float(*)[68]) (sm + 2 * 64 * 132);     // [c][e] 128x68
    float (*Ps)[132] = (float(*)[132])(sm + 2 * 64 * 132 + 128 * 68); // [r][c] 128x132

    const int q0 = blockIdx.x * 128;
    const int hb = blockIdx.y;
    const int h = hb / B, b = hb % B;

    const float* Q = g_qkv + ((size_t)0 * H + h) * BS * E + (size_t)b * S * E;
    const float* K = g_qkv + ((size_t)1 * H + h) * BS * E + (size_t)b * S * E;
    const float* V = g_qkv + ((size_t)2 * H + h) * BS * E + (size_t)b * S * E;
    const float* mask = mask_all + (size_t)(h * B + b) * S * S;

    const int t  = threadIdx.x;
    const int tx = t & 15, ty = t >> 4;

    int rr[8];
    #pragma unroll
    for (int i = 0; i < 8; i++)
        rr[i] = (i < 4) ? (ty * 4 + i) : (64 + ty * 4 + i - 4);

    // Load Q tile transposed: Qs[e][r]
    #pragma unroll
    for (int i = 0; i < 8; i++) {
        int f = i * 256 + t;
        int r = f >> 4, eg = (f & 15) * 4;
        float4 v = *(const float4*)(Q + (size_t)(q0 + r) * E + eg);
        Qs[eg + 0][r] = v.x; Qs[eg + 1][r] = v.y;
        Qs[eg + 2][r] = v.z; Qs[eg + 3][r] = v.w;
    }

    float m_i[8], l_i[8], o[8][4];
    #pragma unroll
    for (int i = 0; i < 8; i++) {
        m_i[i] = -INFINITY; l_i[i] = 0.f;
        o[i][0] = o[i][1] = o[i][2] = o[i][3] = 0.f;
    }

    for (int j0 = 0; j0 < S; j0 += 128) {
        __syncthreads();   // prev iter's readers of Ks/Vs/Ps done
        // K transposed, V direct
        #pragma unroll
        for (int i = 0; i < 8; i++) {
            int f = i * 256 + t;
            int c = f >> 4, eg = (f & 15) * 4;
            float4 v = *(const float4*)(K + (size_t)(j0 + c) * E + eg);
            Ks[eg + 0][c] = v.x; Ks[eg + 1][c] = v.y;
            Ks[eg + 2][c] = v.z; Ks[eg + 3][c] = v.w;
            *(float4*)&Vs[c][eg] = *(const float4*)(V + (size_t)(j0 + c) * E + eg);
        }
        __syncthreads();

        // S = Q K^T (8x8 per thread)
        float s[8][8] = {};
        #pragma unroll 8
        for (int e = 0; e < 64; e++) {
            float qv[8], kv[8];
            *(float4*)&qv[0] = *(float4*)&Qs[e][ty * 4];
            *(float4*)&qv[4] = *(float4*)&Qs[e][64 + ty * 4];
            *(float4*)&kv[0] = *(float4*)&Ks[e][tx * 4];
            *(float4*)&kv[4] = *(float4*)&Ks[e][64 + tx * 4];
            #pragma unroll
            for (int i = 0; i < 8; i++)
                #pragma unroll
                for (int j = 0; j < 8; j++)
                    s[i][j] += qv[i] * kv[j];
        }

        // additive mask
        #pragma unroll
        for (int i = 0; i < 8; i++) {
            const float* mrow = mask + (size_t)(q0 + rr[i]) * S + j0;
            float4 a = *(const float4*)(mrow + tx * 4);
            float4 c = *(const float4*)(mrow + 64 + tx * 4);
            s[i][0] += a.x; s[i][1] += a.y; s[i][2] += a.z; s[i][3] += a.w;
            s[i][4] += c.x; s[i][5] += c.y; s[i][6] += c.z; s[i][7] += c.w;
        }

        // online softmax per row; write P[r][c]
        #pragma unroll
        for (int i = 0; i < 8; i++) {
            float mx = s[i][0];
            #pragma unroll
            for (int j = 1; j < 8; j++) mx = fmaxf(mx, s[i][j]);
            #pragma unroll
            for (int off = 8; off > 0; off >>= 1)
                mx = fmaxf(mx, __shfl_xor_sync(0xffffffffu, mx, off, 16));
            float m_new = fmaxf(m_i[i], mx);
            float alpha = __expf(m_i[i] - m_new);
            float ps = 0.f;
            #pragma unroll
            for (int j = 0; j < 8; j++) { s[i][j] = __expf(s[i][j] - m_new); ps += s[i][j]; }
            #pragma unroll
            for (int off = 8; off > 0; off >>= 1)
                ps += __shfl_xor_sync(0xffffffffu, ps, off, 16);
            l_i[i] = l_i[i] * alpha + ps;
            m_i[i] = m_new;
            o[i][0] *= alpha; o[i][1] *= alpha; o[i][2] *= alpha; o[i][3] *= alpha;
            *(float4*)&Ps[rr[i]][tx * 4]      = *(float4*)&s[i][0];
            *(float4*)&Ps[rr[i]][64 + tx * 4] = *(float4*)&s[i][4];
        }
        __syncthreads();

        // O += P V  (c in groups of 4, float4 P reads)
        #pragma unroll 4
        for (int c0 = 0; c0 < 128; c0 += 4) {
            float4 vv[4];
            #pragma unroll
            for (int q = 0; q < 4; q++)
                vv[q] = *(float4*)&Vs[c0 + q][tx * 4];
            #pragma unroll
            for (int i = 0; i < 8; i++) {
                float4 pv = *(float4*)&Ps[rr[i]][c0];
                o[i][0] += pv.x * vv[0].x; o[i][1] += pv.x * vv[0].y;
                o[i][2] += pv.x * vv[0].z; o[i][3] += pv.x * vv[0].w;
                o[i][0] += pv.y * vv[1].x; o[i][1] += pv.y * vv[1].y;
                o[i][2] += pv.y * vv[1].z; o[i][3] += pv.y * vv[1].w;
                o[i][0] += pv.z * vv[2].x; o[i][1] += pv.z * vv[2].y;
                o[i][2] += pv.z * vv[2].z; o[i][3] += pv.z * vv[2].w;
                o[i][0] += pv.w * vv[3].x; o[i][1] += pv.w * vv[3].y;
                o[i][2] += pv.w * vv[3].z; o[i][3] += pv.w * vv[3].w;
            }
        }
    }

    // epilogue: normalize, write concat-head layout [b][s][h][e]
    #pragma unroll
    for (int i = 0; i < 8; i++) {
        float inv = 1.f / l_i[i];
        int srow = q0 + rr[i];
        float4 v;
        v.x = o[i][0] * inv; v.y = o[i][1] * inv;
        v.z = o[i][2] * inv; v.w = o[i][3] * inv;
        *(float4*)(g_att + ((size_t)(b * S + srow) * H + h) * E + tx * 4) = v;
    }
}

// =====================================================================
// Kernel 3: output projection. 128x128 tile, 8x8 per thread.
// =====================================================================
__global__ __launch_bounds__(256, 2) void proj_kernel(
    const float* __restrict__ Wo, const float* __restrict__ bo,
    float* __restrict__ out)
{
    const int m0 = blockIdx.x * 128;
    const int n0 = blockIdx.y * 128;

    __shared__ float As[32][132];   // [k][m]
    __shared__ float Bs[32][132];   // [k][n]

    const int t  = threadIdx.x;
    const int tx = t & 15, ty = t >> 4;

    float acc[8][8] = {};

    for (int k0 = 0; k0 < D; k0 += 32) {
        #pragma unroll
        for (int i = 0; i < 4; i++) {
            int f = i * 256 + t;
            int r = f >> 3, cg = (f & 7) * 4;
            float4 v = *(const float4*)(g_att + (size_t)(m0 + r) * D + k0 + cg);
            As[cg + 0][r] = v.x; As[cg + 1][r] = v.y;
            As[cg + 2][r] = v.z; As[cg + 3][r] = v.w;
        }
        #pragma unroll
        for (int i = 0; i < 4; i++) {
            int f = i * 256 + t;
            int kk = f >> 5, n = (f & 31) * 4;
            *(float4*)&Bs[kk][n] =
                *(const float4*)(Wo + (size_t)(k0 + kk) * D + n0 + n);
        }
        __syncthreads();

        #pragma unroll 8
        for (int kk = 0; kk < 32; kk++) {
            float av[8], bv_[8];
            *(float4*)&av[0]  = *(float4*)&As[kk][ty * 4];
            *(float4*)&av[4]  = *(float4*)&As[kk][64 + ty * 4];
            *(float4*)&bv_[0] = *(float4*)&Bs[kk][tx * 4];
            *(float4*)&bv_[4] = *(float4*)&Bs[kk][64 + tx * 4];
            #pragma unroll
            for (int i = 0; i < 8; i++)
                #pragma unroll
                for (int j = 0; j < 8; j++)
                    acc[i][j] += av[i] * bv_[j];
        }
        __syncthreads();
    }

    #pragma unroll
    for (int i = 0; i < 8; i++) {
        int m = m0 + ((i < 4) ? (ty * 4 + i) : (64 + ty * 4 + i - 4));
        #pragma unroll
        for (int jg = 0; jg < 2; jg++) {
            int n = n0 + jg * 64 + tx * 4;
            float4 bb = *(const float4*)(bo + n);
            float4 v;
            v.x = acc[i][jg * 4 + 0] + bb.x;
            v.y = acc[i][jg * 4 + 1] + bb.y;
            v.z = acc[i][jg * 4 + 2] + bb.z;
            v.w = acc[i][jg * 4 + 3] + bb.w;
            *(float4*)(out + (size_t)m * D + n) = v;
        }
    }
}

// =====================================================================
// Launch
// =====================================================================
extern "C" void kernel_launch(void* const* d_in, const int* in_sizes, int n_in,
                              void* d_out, int out_size)
{
    const float* x    = (const float*)d_in[0];
    const float* mask = (const float*)d_in[1];
    const float* Wq   = (const float*)d_in[2];
    const float* bq   = (const float*)d_in[3];
    const float* Wk   = (const float*)d_in[4];
    const float* bk   = (const float*)d_in[5];
    const float* Wv   = (const float*)d_in[6];
    const float* bv   = (const float*)d_in[7];
    const float* Wo   = (const float*)d_in[8];
    const float* bo   = (const float*)d_in[9];

    const int smem_attn = (2 * 64 * 132 + 128 * 68 + 128 * 132) * (int)sizeof(float); // 169,984 B
    cudaFuncSetAttribute(attn_kernel, cudaFuncAttributeMaxDynamicSharedMemorySize, smem_attn);

    qkv_kernel <<< dim3(BS / 128, 3 * (H / 2)), 256 >>>(x, Wq, bq, Wk, bk, Wv, bv);
    attn_kernel<<< dim3(S / 128, H * B), 256, smem_attn >>>(mask);
    proj_kernel<<< dim3(BS / 128, D / 128), 256 >>>(Wo, bo, (float*)d_out);
}

// round 4
// speedup vs baseline: 3.2676x; 2.2340x over previous
#include <cuda_runtime.h>
#include <cuda_bf16.h>
#include <math.h>
#include <stdint.h>

#define B 2
#define S 2048
#define D 768
#define H 12
#define E 64
#define BS (B*S)   // 4096
#define PAD 72     // bf16 elements per smem row (144 bytes) -> conflict-free ldmatrix

// ---- scratch (static device globals; no runtime allocation) ----
__device__ __align__(16) __nv_bfloat16 g_x_hi[(size_t)BS * D];
__device__ __align__(16) __nv_bfloat16 g_x_lo[(size_t)BS * D];
__device__ __align__(16) __nv_bfloat16 g_wt_hi[(size_t)3 * H * E * D]; // [which][h*E+e][k]
__device__ __align__(16) __nv_bfloat16 g_wt_lo[(size_t)3 * H * E * D];
__device__ __align__(16) __nv_bfloat16 g_wo_hi[(size_t)D * D];         // [n][k]
__device__ __align__(16) __nv_bfloat16 g_wo_lo[(size_t)D * D];
__device__ __align__(16) __nv_bfloat16 g_qkvb_hi[(size_t)3 * H * BS * E]; // [which][h][b*S+s][e]
__device__ __align__(16) __nv_bfloat16 g_qkvb_lo[(size_t)3 * H * BS * E];
__device__ __align__(16) __nv_bfloat16 g_att_hi[(size_t)BS * D];       // [b*S+s][h*E+e]
__device__ __align__(16) __nv_bfloat16 g_att_lo[(size_t)BS * D];

// ======================= helpers =======================
__device__ __forceinline__ uint32_t smem_u32(const void* p) {
    uint32_t a;
    asm("{ .reg .u64 t; cvta.to.shared.u64 t, %1; cvt.u32.u64 %0, t; }" : "=r"(a) : "l"(p));
    return a;
}
__device__ __forceinline__ void ldsm4(uint32_t* r, uint32_t a) {
    asm volatile("ldmatrix.sync.aligned.m8n8.x4.shared.b16 {%0,%1,%2,%3}, [%4];"
        : "=r"(r[0]), "=r"(r[1]), "=r"(r[2]), "=r"(r[3]) : "r"(a));
}
__device__ __forceinline__ void ldsm4t(uint32_t* r, uint32_t a) {
    asm volatile("ldmatrix.sync.aligned.m8n8.x4.trans.shared.b16 {%0,%1,%2,%3}, [%4];"
        : "=r"(r[0]), "=r"(r[1]), "=r"(r[2]), "=r"(r[3]) : "r"(a));
}
__device__ __forceinline__ void mma16816(float* c, const uint32_t* a, uint32_t b0, uint32_t b1) {
    asm volatile("mma.sync.aligned.m16n8k16.row.col.f32.bf16.bf16.f32 "
        "{%0,%1,%2,%3}, {%4,%5,%6,%7}, {%8,%9}, {%0,%1,%2,%3};"
        : "+f"(c[0]), "+f"(c[1]), "+f"(c[2]), "+f"(c[3])
        : "r"(a[0]), "r"(a[1]), "r"(a[2]), "r"(a[3]), "r"(b0), "r"(b1));
}
__device__ __forceinline__ void split2(float x, float y, uint32_t& hi, uint32_t& lo) {
    __nv_bfloat162 h = __floats2bfloat162_rn(x, y);
    float hx = __bfloat162float(h.x), hy = __bfloat162float(h.y);
    __nv_bfloat162 l = __floats2bfloat162_rn(x - hx, y - hy);
    hi = *(uint32_t*)&h; lo = *(uint32_t*)&l;
}

// load 128 rows x 64 bf16 (row stride ldg elems) into padded smem tile (256 threads)
__device__ __forceinline__ void load_tile_pad(const __nv_bfloat16* __restrict__ g, int ldg,
                                              __nv_bfloat16* s, int t)
{
    #pragma unroll
    for (int i = 0; i < 4; i++) {
        int f = i * 256 + t;
        int r = f >> 3, c8 = (f & 7) * 8;
        *(uint4*)(s + r * PAD + c8) = *(const uint4*)(g + (size_t)r * ldg + c8);
    }
}

// ======================= prep: fp32 -> bf16 hi/lo =======================
__global__ void split_kernel(const float* __restrict__ src,
                             __nv_bfloat16* __restrict__ hi, __nv_bfloat16* __restrict__ lo, int n)
{
    int i = blockIdx.x * 256 + threadIdx.x;
    if (i < n) {
        float v = src[i];
        __nv_bfloat16 h = __float2bfloat16(v);
        hi[i] = h;
        lo[i] = __float2bfloat16(v - __bfloat162float(h));
    }
}
__global__ void wsplit_kernel(const float* __restrict__ W,
                              __nv_bfloat16* __restrict__ hi, __nv_bfloat16* __restrict__ lo)
{
    int idx = blockIdx.x * 256 + threadIdx.x;
    if (idx >= H * E * D) return;
    int k = idx % D, r = idx / D;
    int h = r / E, e = r % E;
    float v = W[((size_t)h * D + k) * E + e];
    __nv_bfloat16 hv = __float2bfloat16(v);
    hi[idx] = hv;
    lo[idx] = __float2bfloat16(v - __bfloat162float(hv));
}
__global__ void wosplit_kernel(const float* __restrict__ Wo,
                               __nv_bfloat16* __restrict__ hi, __nv_bfloat16* __restrict__ lo)
{
    int idx = blockIdx.x * 256 + threadIdx.x;
    if (idx >= D * D) return;
    int k = idx % D, n = idx / D;
    float v = Wo[(size_t)k * D + n];
    __nv_bfloat16 hv = __float2bfloat16(v);
    hi[idx] = hv;
    lo[idx] = __float2bfloat16(v - __bfloat162float(hv));
}

// ======================= shared GEMM core (mma.sync) =======================
// 256 threads, warp grid 4(M)x2(N); warp tile 32x64; CTA tile 128x128, k-chunk 64.
// acc[2][8][4]: [m-frag][n-tile][reg]
struct GemmAcc { float a[2][8][4]; };

__device__ __forceinline__ void gemm_chunks(
    const __nv_bfloat16* Ah_g, const __nv_bfloat16* Al_g, int lda,
    const __nv_bfloat16* Bh_g, const __nv_bfloat16* Bl_g, int ldb,
    char* smem, int t, GemmAcc& C)
{
    __nv_bfloat16* sAh = (__nv_bfloat16*)(smem);
    __nv_bfloat16* sAl = (__nv_bfloat16*)(smem + 18432);
    __nv_bfloat16* sBh = (__nv_bfloat16*)(smem + 36864);
    __nv_bfloat16* sBl = (__nv_bfloat16*)(smem + 55296);
    const uint32_t uAh = smem_u32(sAh), uAl = smem_u32(sAl);
    const uint32_t uBh = smem_u32(sBh), uBl = smem_u32(sBl);

    const int lane = t & 31, wid = t >> 5;
    const int mrow0 = (wid >> 1) * 32;
    const int ncol0 = (wid & 1) * 64;

    const uint32_t a_off = (uint32_t)(mrow0 + (lane & 15)) * 144 + ((lane & 16) >> 1) * 2;
    const uint32_t b_off = (uint32_t)(ncol0 + (lane & 7) + ((lane & 16) >> 1)) * 144 + (lane & 8) * 2;

    #pragma unroll 1
    for (int c = 0; c < 12; c++) {
        __syncthreads();
        load_tile_pad(Ah_g + c * 64, lda, sAh, t);
        load_tile_pad(Al_g + c * 64, lda, sAl, t);
        load_tile_pad(Bh_g + c * 64, ldb, sBh, t);
        load_tile_pad(Bl_g + c * 64, ldb, sBl, t);
        __syncthreads();

        #pragma unroll
        for (int ks = 0; ks < 4; ks++) {
            uint32_t ah0[4], ah1[4], al0[4], al1[4];
            const uint32_t ao = a_off + ks * 32;   // ks*16 elems = 32 bytes
            ldsm4(ah0, uAh + ao);
            ldsm4(ah1, uAh + ao + 16 * 144);
            ldsm4(al0, uAl + ao);
            ldsm4(al1, uAl + ao + 16 * 144);
            #pragma unroll
            for (int np = 0; np < 4; np++) {
                uint32_t bh[4], bl[4];
                const uint32_t bo = b_off + np * 16 * 144 + ks * 32;
                ldsm4(bh, uBh + bo);
                ldsm4(bl, uBl + bo);
                mma16816(C.a[0][2*np],   ah0, bh[0], bh[1]);
                mma16816(C.a[0][2*np],   ah0, bl[0], bl[1]);
                mma16816(C.a[0][2*np],   al0, bh[0], bh[1]);
                mma16816(C.a[0][2*np+1], ah0, bh[2], bh[3]);
                mma16816(C.a[0][2*np+1], ah0, bl[2], bl[3]);
                mma16816(C.a[0][2*np+1], al0, bh[2], bh[3]);
                mma16816(C.a[1][2*np],   ah1, bh[0], bh[1]);
                mma16816(C.a[1][2*np],   ah1, bl[0], bl[1]);
                mma16816(C.a[1][2*np],   al1, bh[0], bh[1]);
                mma16816(C.a[1][2*np+1], ah1, bh[2], bh[3]);
                mma16816(C.a[1][2*np+1], ah1, bl[2], bl[3]);
                mma16816(C.a[1][2*np+1], al1, bh[2], bh[3]);
            }
        }
    }
}

// ======================= QKV GEMM kernel =======================
__global__ __launch_bounds__(256) void qkv_mma_kernel(
    const float* __restrict__ bq, const float* __restrict__ bk, const float* __restrict__ bv)
{
    extern __shared__ __align__(16) char smem[];
    const int t = threadIdx.x, lane = t & 31, wid = t >> 5;
    const int m0 = blockIdx.x * 128;
    const int zz = blockIdx.y;
    const int which = zz / (H / 2);
    const int h0 = (zz % (H / 2)) * 2;

    GemmAcc C;
    #pragma unroll
    for (int i = 0; i < 2; i++)
        #pragma unroll
        for (int j = 0; j < 8; j++)
            C.a[i][j][0] = C.a[i][j][1] = C.a[i][j][2] = C.a[i][j][3] = 0.f;

    gemm_chunks(g_x_hi + (size_t)m0 * D, g_x_lo + (size_t)m0 * D, D,
                g_wt_hi + ((size_t)which * H + h0) * E * D,
                g_wt_lo + ((size_t)which * H + h0) * E * D, D,
                smem, t, C);

    const float* bias = (which == 0) ? bq : (which == 1) ? bk : bv;
    const int g = lane >> 2, j2 = (lane & 3) * 2;
    const int mrow0 = (wid >> 1) * 32, ncol0 = (wid & 1) * 64;
    __nv_bfloat16* dh = g_qkvb_hi;
    __nv_bfloat16* dl = g_qkvb_lo;

    #pragma unroll
    for (int mi = 0; mi < 2; mi++) {
        const int mA = m0 + mrow0 + mi * 16 + g;
        #pragma unroll
        for (int nt = 0; nt < 8; nt++) {
            const int n = ncol0 + nt * 8 + j2;
            const int hh = h0 + (n >> 6), e = n & 63;
            const float b0f = bias[hh * E + e], b1f = bias[hh * E + e + 1];
            size_t base = ((size_t)which * H + hh) * BS * E + e;
            uint32_t hi, lo;
            split2(C.a[mi][nt][0] + b0f, C.a[mi][nt][1] + b1f, hi, lo);
            *(uint32_t*)(dh + base + (size_t)mA * E) = hi;
            *(uint32_t*)(dl + base + (size_t)mA * E) = lo;
            split2(C.a[mi][nt][2] + b0f, C.a[mi][nt][3] + b1f, hi, lo);
            *(uint32_t*)(dh + base + (size_t)(mA + 8) * E) = hi;
            *(uint32_t*)(dl + base + (size_t)(mA + 8) * E) = lo;
        }
    }
}

// ======================= output projection kernel =======================
__global__ __launch_bounds__(256) void proj_mma_kernel(
    const float* __restrict__ bo, float* __restrict__ out)
{
    extern __shared__ __align__(16) char smem[];
    const int t = threadIdx.x, lane = t & 31, wid = t >> 5;
    const int m0 = blockIdx.x * 128;
    const int n0 = blockIdx.y * 128;

    GemmAcc C;
    #pragma unroll
    for (int i = 0; i < 2; i++)
        #pragma unroll
        for (int j = 0; j < 8; j++)
            C.a[i][j][0] = C.a[i][j][1] = C.a[i][j][2] = C.a[i][j][3] = 0.f;

    gemm_chunks(g_att_hi + (size_t)m0 * D, g_att_lo + (size_t)m0 * D, D,
                g_wo_hi + (size_t)n0 * D, g_wo_lo + (size_t)n0 * D, D,
                smem, t, C);

    const int g = lane >> 2, j2 = (lane & 3) * 2;
    const int mrow0 = (wid >> 1) * 32, ncol0 = (wid & 1) * 64;

    #pragma unroll
    for (int mi = 0; mi < 2; mi++) {
        const int mA = m0 + mrow0 + mi * 16 + g;
        #pragma unroll
        for (int nt = 0; nt < 8; nt++) {
            const int n = n0 + ncol0 + nt * 8 + j2;
            const float b0f = bo[n], b1f = bo[n + 1];
            float2 v0 = { C.a[mi][nt][0] + b0f, C.a[mi][nt][1] + b1f };
            float2 v1 = { C.a[mi][nt][2] + b0f, C.a[mi][nt][3] + b1f };
            *(float2*)(out + (size_t)mA * D + n) = v0;
            *(float2*)(out + (size_t)(mA + 8) * D + n) = v1;
        }
    }
}

// ======================= flash attention (mma.sync) =======================
// 256 threads, 8 warps; warp tile 16(q-rows) x 128(kv). q-tile 128, kv chunks of 128.
__global__ __launch_bounds__(256) void attn_kernel(const float* __restrict__ mask_all)
{
    extern __shared__ __align__(16) char smem[];
    __nv_bfloat16* sQh = (__nv_bfloat16*)(smem);
    __nv_bfloat16* sQl = (__nv_bfloat16*)(smem + 18432);
    __nv_bfloat16* sKh = (__nv_bfloat16*)(smem + 36864);
    __nv_bfloat16* sKl = (__nv_bfloat16*)(smem + 55296);
    __nv_bfloat16* sVh = (__nv_bfloat16*)(smem + 73728);
    __nv_bfloat16* sVl = (__nv_bfloat16*)(smem + 92160);
    const uint32_t uQh = smem_u32(sQh), uQl = smem_u32(sQl);
    const uint32_t uKh = smem_u32(sKh), uKl = smem_u32(sKl);
    const uint32_t uVh = smem_u32(sVh), uVl = smem_u32(sVl);

    const int q0 = blockIdx.x * 128;
    const int hb = blockIdx.y;
    const int h = hb / B, b = hb % B;

    const __nv_bfloat16* Qh_g = g_qkvb_hi + ((size_t)0 * H + h) * BS * E + (size_t)(b * S + q0) * E;
    const __nv_bfloat16* Ql_g = g_qkvb_lo + ((size_t)0 * H + h) * BS * E + (size_t)(b * S + q0) * E;
    const __nv_bfloat16* Kh_g = g_qkvb_hi + ((size_t)1 * H + h) * BS * E + (size_t)b * S * E;
    const __nv_bfloat16* Kl_g = g_qkvb_lo + ((size_t)1 * H + h) * BS * E + (size_t)b * S * E;
    const __nv_bfloat16* Vh_g = g_qkvb_hi + ((size_t)2 * H + h) * BS * E + (size_t)b * S * E;
    const __nv_bfloat16* Vl_g = g_qkvb_lo + ((size_t)2 * H + h) * BS * E + (size_t)b * S * E;
    const float* mask = mask_all + (size_t)(h * B + b) * S * S;

    const int t = threadIdx.x, lane = t & 31, wid = t >> 5;
    const int g = lane >> 2, j2 = (lane & 3) * 2;
    const int r0 = wid * 16;

    // Q tiles -> smem -> register fragments (hoisted for whole kernel)
    load_tile_pad(Qh_g, E, sQh, t);
    load_tile_pad(Ql_g, E, sQl, t);
    __syncthreads();
    uint32_t qh[4][4], ql[4][4];
    {
        const uint32_t ao = (uint32_t)(r0 + (lane & 15)) * 144 + ((lane & 16) >> 1) * 2;
        #pragma unroll
        for (int ks = 0; ks < 4; ks++) {
            ldsm4(qh[ks], uQh + ao + ks * 32);
            ldsm4(ql[ks], uQl + ao + ks * 32);
        }
    }

    float m_a = -INFINITY, m_b = -INFINITY, l_a = 0.f, l_b = 0.f;
    float o[8][4];
    #pragma unroll
    for (int et = 0; et < 8; et++)
        o[et][0] = o[et][1] = o[et][2] = o[et][3] = 0.f;

    const uint32_t kb_off = (uint32_t)((lane & 7) + ((lane & 16) >> 1)) * 144 + (lane & 8) * 2;
    const uint32_t vb_off = (uint32_t)(lane & 15) * 144 + ((lane & 16) >> 1) * 2;

    #pragma unroll 1
    for (int j0 = 0; j0 < S; j0 += 128) {
        __syncthreads();
        load_tile_pad(Kh_g + (size_t)j0 * E, E, sKh, t);
        load_tile_pad(Kl_g + (size_t)j0 * E, E, sKl, t);
        load_tile_pad(Vh_g + (size_t)j0 * E, E, sVh, t);
        load_tile_pad(Vl_g + (size_t)j0 * E, E, sVl, t);
        __syncthreads();

        // ---- S = Q K^T (hi/lo 3-product) ----
        float s[16][4];
        #pragma unroll
        for (int nt = 0; nt < 16; nt++)
            s[nt][0] = s[nt][1] = s[nt][2] = s[nt][3] = 0.f;

        #pragma unroll
        for (int ks = 0; ks < 4; ks++) {
            #pragma unroll
            for (int np = 0; np < 8; np++) {
                uint32_t bh[4], bl[4];
                const uint32_t bo = kb_off + np * 16 * 144 + ks * 32;
                ldsm4(bh, uKh + bo);
                ldsm4(bl, uKl + bo);
                mma16816(s[2*np],   qh[ks], bh[0], bh[1]);
                mma16816(s[2*np],   qh[ks], bl[0], bl[1]);
                mma16816(s[2*np],   ql[ks], bh[0], bh[1]);
                mma16816(s[2*np+1], qh[ks], bh[2], bh[3]);
                mma16816(s[2*np+1], qh[ks], bl[2], bl[3]);
                mma16816(s[2*np+1], ql[ks], bh[2], bh[3]);
            }
        }

        // ---- additive mask ----
        const float* mra = mask + (size_t)(q0 + r0 + g) * S + j0 + j2;
        const float* mrb = mra + 8 * S;
        #pragma unroll
        for (int nt = 0; nt < 16; nt++) {
            float2 ma = *(const float2*)(mra + nt * 8);
            float2 mb = *(const float2*)(mrb + nt * 8);
            s[nt][0] += ma.x; s[nt][1] += ma.y;
            s[nt][2] += mb.x; s[nt][3] += mb.y;
        }

        // ---- online softmax (rows g and g+8 of this warp's 16) ----
        float mxa = -INFINITY, mxb = -INFINITY;
        #pragma unroll
        for (int nt = 0; nt < 16; nt++) {
            mxa = fmaxf(mxa, fmaxf(s[nt][0], s[nt][1]));
            mxb = fmaxf(mxb, fmaxf(s[nt][2], s[nt][3]));
        }
        mxa = fmaxf(mxa, __shfl_xor_sync(0xffffffffu, mxa, 1));
        mxa = fmaxf(mxa, __shfl_xor_sync(0xffffffffu, mxa, 2));
        mxb = fmaxf(mxb, __shfl_xor_sync(0xffffffffu, mxb, 1));
        mxb = fmaxf(mxb, __shfl_xor_sync(0xffffffffu, mxb, 2));

        const float mna = fmaxf(m_a, mxa), mnb = fmaxf(m_b, mxb);
        const float aa = __expf(m_a - mna), ab = __expf(m_b - mnb);
        float sa = 0.f, sb = 0.f;
        #pragma unroll
        for (int nt = 0; nt < 16; nt++) {
            s[nt][0] = __expf(s[nt][0] - mna); sa += s[nt][0];
            s[nt][1] = __expf(s[nt][1] - mna); sa += s[nt][1];
            s[nt][2] = __expf(s[nt][2] - mnb); sb += s[nt][2];
            s[nt][3] = __expf(s[nt][3] - mnb); sb += s[nt][3];
        }
        sa += __shfl_xor_sync(0xffffffffu, sa, 1);
        sa += __shfl_xor_sync(0xffffffffu, sa, 2);
        sb += __shfl_xor_sync(0xffffffffu, sb, 1);
        sb += __shfl_xor_sync(0xffffffffu, sb, 2);
        l_a = l_a * aa + sa; l_b = l_b * ab + sb;
        m_a = mna; m_b = mnb;
        #pragma unroll
        for (int et = 0; et < 8; et++) {
            o[et][0] *= aa; o[et][1] *= aa;
            o[et][2] *= ab; o[et][3] *= ab;
        }

        // ---- O += P V (P split hi/lo on the fly; S-frag == A-frag layout) ----
        #pragma unroll
        for (int ks2 = 0; ks2 < 8; ks2++) {
            const int nt0 = 2 * ks2, nt1 = nt0 + 1;
            uint32_t a_hi[4], a_lo[4];
            split2(s[nt0][0], s[nt0][1], a_hi[0], a_lo[0]);
            split2(s[nt0][2], s[nt0][3], a_hi[1], a_lo[1]);
            split2(s[nt1][0], s[nt1][1], a_hi[2], a_lo[2]);
            split2(s[nt1][2], s[nt1][3], a_hi[3], a_lo[3]);
            #pragma unroll
            for (int ep = 0; ep < 4; ep++) {
                uint32_t vh[4], vl[4];
                const uint32_t vo = vb_off + ks2 * 16 * 144 + ep * 32;
                ldsm4t(vh, uVh + vo);
                ldsm4t(vl, uVl + vo);
                mma16816(o[2*ep],   a_hi, vh[0], vh[1]);
                mma16816(o[2*ep],   a_lo, vh[0], vh[1]);
                mma16816(o[2*ep],   a_hi, vl[0], vl[1]);
                mma16816(o[2*ep+1], a_hi, vh[2], vh[3]);
                mma16816(o[2*ep+1], a_lo, vh[2], vh[3]);
                mma16816(o[2*ep+1], a_hi, vl[2], vl[3]);
            }
        }
    }

    // ---- epilogue: normalize, split hi/lo, concat-head layout ----
    const float ia = 1.f / l_a, ib = 1.f / l_b;
    const int rowA = q0 + r0 + g, rowB = rowA + 8;
    #pragma unroll
    for (int et = 0; et < 8; et++) {
        const size_t col = (size_t)h * E + et * 8 + j2;
        uint32_t hi, lo;
        split2(o[et][0] * ia, o[et][1] * ia, hi, lo);
        *(uint32_t*)(g_att_hi + (size_t)(b * S + rowA) * D + col) = hi;
        *(uint32_t*)(g_att_lo + (size_t)(b * S + rowA) * D + col) = lo;
        split2(o[et][2] * ib, o[et][3] * ib, hi, lo);
        *(uint32_t*)(g_att_hi + (size_t)(b * S + rowB) * D + col) = hi;
        *(uint32_t*)(g_att_lo + (size_t)(b * S + rowB) * D + col) = lo;
    }
}

// ======================= Launch =======================
extern "C" void kernel_launch(void* const* d_in, const int* in_sizes, int n_in,
                              void* d_out, int out_size)
{
    const float* x    = (const float*)d_in[0];
    const float* mask = (const float*)d_in[1];
    const float* Wq   = (const float*)d_in[2];
    const float* bq   = (const float*)d_in[3];
    const float* Wk   = (const float*)d_in[4];
    const float* bk   = (const float*)d_in[5];
    const float* Wv   = (const float*)d_in[6];
    const float* bv   = (const float*)d_in[7];
    const float* Wo   = (const float*)d_in[8];
    const float* bo   = (const float*)d_in[9];

    __nv_bfloat16 *xhi, *xlo, *wthi, *wtlo, *wohi, *wolo;
    cudaGetSymbolAddress((void**)&xhi,  g_x_hi);
    cudaGetSymbolAddress((void**)&xlo,  g_x_lo);
    cudaGetSymbolAddress((void**)&wthi, g_wt_hi);
    cudaGetSymbolAddress((void**)&wtlo, g_wt_lo);
    cudaGetSymbolAddress((void**)&wohi, g_wo_hi);
    cudaGetSymbolAddress((void**)&wolo, g_wo_lo);

    const int smem_gemm = 4 * 128 * PAD * 2;   // 73,728 B
    const int smem_attn = 6 * 128 * PAD * 2;   // 110,592 B
    cudaFuncSetAttribute(qkv_mma_kernel,  cudaFuncAttributeMaxDynamicSharedMemorySize, smem_gemm);
    cudaFuncSetAttribute(proj_mma_kernel, cudaFuncAttributeMaxDynamicSharedMemorySize, smem_gemm);
    cudaFuncSetAttribute(attn_kernel,     cudaFuncAttributeMaxDynamicSharedMemorySize, smem_attn);

    const int HED = H * E * D;
    split_kernel  <<< (BS * D + 255) / 256, 256 >>>(x, xhi, xlo, BS * D);
    wsplit_kernel <<< (HED + 255) / 256, 256 >>>(Wq, wthi + 0 * (size_t)HED, wtlo + 0 * (size_t)HED);
    wsplit_kernel <<< (HED + 255) / 256, 256 >>>(Wk, wthi + 1 * (size_t)HED, wtlo + 1 * (size_t)HED);
    wsplit_kernel <<< (HED + 255) / 256, 256 >>>(Wv, wthi + 2 * (size_t)HED, wtlo + 2 * (size_t)HED);
    wosplit_kernel<<< (D * D + 255) / 256, 256 >>>(Wo, wohi, wolo);

    qkv_mma_kernel <<< dim3(BS / 128, 3 * (H / 2)), 256, smem_gemm >>>(bq, bk, bv);
    attn_kernel    <<< dim3(S / 128, H * B), 256, smem_attn >>>(mask);
    proj_mma_kernel<<< dim3(BS / 128, D / 128), 256, smem_gemm >>>(bo, (float*)d_out);
}